// round 7
// baseline (speedup 1.0000x reference)
#include <cuda_runtime.h>
#include <cuda_fp16.h>
#include <cstdint>

// Problem constants: B=256, D=256, F=512
#define Bc 256
#define Dc 256
#define Fc 512
#define P_T 0.05f

// ---------------------------------------------------------------------------
// Scratch (static device memory, 16B aligned)
// ---------------------------------------------------------------------------
#define DEVARR __device__ __align__(16)
DEVARR __half g_zT[Fc * Bc];     // z^T  (F,B) K-major fp16
DEVARR __half g_xT[Dc * Bc];     // x^T  (D,B)
DEVARR __half g_uT[Fc * Bc];     // u^T  (F,B)
DEVARR __half g_tdT[Fc * Bc];    // td^T (F,B)
DEVARR __half g_G16[Fc * Fc];    // G fp16 (F,F) K(=j)-major rows
DEVARR float g_XZ[Dc * Fc];      // mean_b x z (fp32)
DEVARR float g_zbp[8][Fc];       // zbar partials (raw sums of 32 b's)
DEVARR float g_rpart[4][Fc];     // G row-sum partials per 128-col tile (raw)
DEVARR float g_diag[Fc];         // p - mu_t[i,i]

// m16n8k16 f16 MMA, fp32 accumulators (base PTX, works on sm_100 target)
__device__ __forceinline__ void mma16816(float* c, const uint32_t* a, const uint32_t* b) {
    asm volatile(
        "mma.sync.aligned.m16n8k16.row.col.f32.f16.f16.f32 "
        "{%0,%1,%2,%3}, {%4,%5,%6,%7}, {%8,%9}, {%0,%1,%2,%3};"
        : "+f"(c[0]), "+f"(c[1]), "+f"(c[2]), "+f"(c[3])
        : "r"(a[0]), "r"(a[1]), "r"(a[2]), "r"(a[3]), "r"(b[0]), "r"(b[1]));
}

// ---------------------------------------------------------------------------
// conv_k: transpose+convert z,x,u,td -> fp16 K-major; zbar partials.
// ---------------------------------------------------------------------------
__global__ void __launch_bounds__(256) conv_k(
    const float* __restrict__ z, const float* __restrict__ x,
    const float* __restrict__ u, const float* __restrict__ td)
{
    const int bb = blockIdx.x, tid = threadIdx.x;
    const float* src; __half* dst; int Fs, t; bool do_zbar = false;
    if (bb < 128)      { src = z;  dst = g_zT;  Fs = Fc; t = bb;       do_zbar = true; }
    else if (bb < 256) { src = u;  dst = g_uT;  Fs = Fc; t = bb - 128; }
    else if (bb < 384) { src = td; dst = g_tdT; Fs = Fc; t = bb - 256; }
    else               { src = x;  dst = g_xT;  Fs = Dc; t = bb - 384; }
    const int nf = Fs / 32;
    const int b0 = (t / nf) * 32, f0 = (t % nf) * 32;

    __shared__ float T[32][33];
    const int c = tid & 31, r0 = tid >> 5;
#pragma unroll
    for (int q = 0; q < 4; q++) {
        int r = r0 + 8 * q;
        T[r][c] = src[(b0 + r) * Fs + f0 + c];
    }
    __syncthreads();
#pragma unroll
    for (int q = 0; q < 4; q++) {
        int cc = r0 + 8 * q;
        dst[(f0 + cc) * Bc + b0 + c] = __float2half(T[c][cc]);
    }
    if (do_zbar && tid < 32) {
        float s = 0.f;
#pragma unroll
        for (int rr = 0; rr < 32; rr++) s += T[rr][tid];
        g_zbp[b0 >> 5][f0 + tid] = s;
    }
}

// ---------------------------------------------------------------------------
// mma1_k: 40 CTAs, 128x128 tiles, K=256. 8 warps, warp = 64x32 (mf=4, nf=4).
//   bb [0,16):  M  = z'z /B  -> dmu, G16, rpart, diag/dbf/dbp
//   bb [16,32): KP = u'td /B -> o_dkp
//   bb [32,40): XZ = x'z /B  -> g_XZ
// Operands direct-from-global (K-major fp16), accumulators in registers.
// ---------------------------------------------------------------------------
__global__ void __launch_bounds__(256) mma1_k(
    const float* __restrict__ mu,
    float* __restrict__ o_dmu, float* __restrict__ o_dbf,
    float* __restrict__ o_dbp, float* __restrict__ o_dkp)
{
    const int bb = blockIdx.x, tid = threadIdx.x;
    const int wid = tid >> 5, lane = tid & 31;
    const int gid = lane >> 2, tig = lane & 3;
    const int wm = wid >> 2, wn = wid & 3;       // 2x4 warp grid

    int kind, m0, n0;
    const __half *A, *B;
    if (bb < 16)      { kind = 0; int t = bb;      m0 = (t >> 2) * 128; n0 = (t & 3) * 128; A = g_zT; B = g_zT; }
    else if (bb < 32) { kind = 1; int t = bb - 16; m0 = (t >> 2) * 128; n0 = (t & 3) * 128; A = g_uT; B = g_tdT; }
    else              { kind = 2; int t = bb - 32; m0 = (t >> 2) * 128; n0 = (t & 3) * 128; A = g_xT; B = g_zT; }

    __shared__ float s_rsum[128];
    if (tid < 128) s_rsum[tid] = 0.f;
    __syncthreads();

    // Warp sub-tile origin
    const int mw = m0 + wm * 64;       // 64 rows (4 mf of 16)
    const int nw = n0 + wn * 32;       // 32 cols (4 nf of 8)

    float acc[4][4][4];
#pragma unroll
    for (int i = 0; i < 4; i++)
#pragma unroll
        for (int j = 0; j < 4; j++)
#pragma unroll
            for (int q = 0; q < 4; q++) acc[i][j][q] = 0.f;

    // Per-thread base pointers (K-major: row*Bc + k)
    const __half* Ab = A + (mw + gid) * Bc + 2 * tig;
    const __half* Bb = B + (nw + gid) * Bc + 2 * tig;

    for (int k0 = 0; k0 < Bc; k0 += 16) {
        uint32_t a[4][4], b[4][2];
#pragma unroll
        for (int mf = 0; mf < 4; mf++) {
            const __half* p = Ab + mf * 16 * Bc + k0;
            a[mf][0] = *(const uint32_t*)(p);
            a[mf][1] = *(const uint32_t*)(p + 8 * Bc);
            a[mf][2] = *(const uint32_t*)(p + 8);
            a[mf][3] = *(const uint32_t*)(p + 8 * Bc + 8);
        }
#pragma unroll
        for (int nf = 0; nf < 4; nf++) {
            const __half* p = Bb + nf * 8 * Bc + k0;
            b[nf][0] = *(const uint32_t*)(p);
            b[nf][1] = *(const uint32_t*)(p + 8);
        }
#pragma unroll
        for (int mf = 0; mf < 4; mf++)
#pragma unroll
            for (int nf = 0; nf < 4; nf++)
                mma16816(acc[mf][nf], a[mf], b[nf]);
    }

    // Fused epilogue (register accumulators -> global), float2 granularity.
    const float invB = 1.0f / Bc;
#pragma unroll
    for (int mf = 0; mf < 4; mf++) {
#pragma unroll
        for (int h = 0; h < 2; h++) {
            const int gr = mw + mf * 16 + gid + h * 8;
            float rowsum = 0.f;
#pragma unroll
            for (int nf = 0; nf < 4; nf++) {
                const int gc = nw + nf * 8 + 2 * tig;
                const int idx = gr * Fc + gc;
                float v0 = acc[mf][nf][h * 2 + 0];
                float v1 = acc[mf][nf][h * 2 + 1];
                if (kind == 0) {
                    float raw0 = v0 * invB, raw1 = v1 * invB;
                    float2 muv = *(const float2*)&mu[idx];
                    float mut0 = 0.95f * muv.x + 0.05f * raw0;
                    float mut1 = 0.95f * muv.y + 0.05f * raw1;
                    float2 dm = {0.05f * (raw0 - muv.x), 0.05f * (raw1 - muv.y)};
                    *(float2*)&o_dmu[idx] = dm;
                    float G0 = (P_T * P_T - mut0) * raw0;
                    float G1 = (P_T * P_T - mut1) * raw1;
                    *(__half2*)&g_G16[idx] = __floats2half2_rn(G0, G1);
                    rowsum += G0 + G1;
                    if (m0 == n0) {
                        if (gr == gc) {
                            float db = P_T - mut0;
                            g_diag[gr] = db; o_dbf[gr] = db; o_dbp[gr] = db;
                        } else if (gr == gc + 1) {
                            float db = P_T - mut1;
                            g_diag[gr] = db; o_dbf[gr] = db; o_dbp[gr] = db;
                        }
                    }
                } else if (kind == 1) {
                    float2 o = {v0 * invB, v1 * invB};
                    *(float2*)&o_dkp[idx] = o;
                } else {
                    float2 o = {v0 * invB, v1 * invB};
                    *(float2*)&g_XZ[idx] = o;
                }
            }
            if (kind == 0) {
                // reduce across the 4 tig lanes sharing this row
                rowsum += __shfl_xor_sync(0xffffffffu, rowsum, 1);
                rowsum += __shfl_xor_sync(0xffffffffu, rowsum, 2);
                if (tig == 0) atomicAdd(&s_rsum[gr - m0], rowsum);
            }
        }
    }
    if (kind == 0) {
        __syncthreads();
        if (tid < 128) g_rpart[n0 >> 7][m0 + tid] = s_rsum[tid];
    }
}

// ---------------------------------------------------------------------------
// mma2_k: 16 CTAs, 64x128 tiles, K=512. 8 warps (2x4), warp = 32x32 (mf=2,nf=4).
// cross[d,i] = sum_j wf16[d,j] * G16[i,j];  full dkf epilogue fused.
// ---------------------------------------------------------------------------
__global__ void __launch_bounds__(256) mma2_k(
    const float* __restrict__ wf32, float* __restrict__ o_dkf)
{
    const int bb = blockIdx.x, tid = threadIdx.x;
    const int wid = tid >> 5, lane = tid & 31;
    const int gid = lane >> 2, tig = lane & 3;
    const int wm = wid >> 2, wn = wid & 3;       // 2x4 warp grid

    const int d0 = (bb >> 2) * 64;               // 4 row-tiles of 64
    const int n0 = (bb & 3) * 128;               // 4 col-tiles of 128

    __shared__ float s_diag[128], s_zbar[128], s_r[128];
    if (tid < 128) {
        int i = n0 + tid;
        float zs = 0.f;
#pragma unroll
        for (int p = 0; p < 8; p++) zs += g_zbp[p][i];
        s_zbar[tid] = zs * (1.0f / Bc);
        float rr = 0.f;
#pragma unroll
        for (int q = 0; q < 4; q++) rr += g_rpart[q][i];
        s_r[tid] = rr * (1.0f / Fc);
        s_diag[tid] = g_diag[i];
    }
    __syncthreads();

    const int mw = d0 + wm * 32;                 // 32 rows (2 mf)
    const int nw = n0 + wn * 32;                 // 32 cols (4 nf)

    float acc[2][4][4];
#pragma unroll
    for (int i = 0; i < 2; i++)
#pragma unroll
        for (int j = 0; j < 4; j++)
#pragma unroll
            for (int q = 0; q < 4; q++) acc[i][j][q] = 0.f;

    // wf16 built on the fly? No: A operand is wf in fp16, K-major (D,F) - we
    // convert inline from fp32? mma needs fp16 regs; convert per load:
    // cheaper to read wf32 and cvt (K=512 -> 16 a-regs per kstep... ) Instead
    // we precompute nothing: read two fp32 and pack. 2xLDG.64 per reg. Simpler:
    // read float2 and cvt.
    const float* Awf = wf32;                     // (Dc, Fc) row-major, k=Fc
    const __half* Bg = g_G16;                    // (Fc, Fc) row-major, k=Fc

    const float* Ab = Awf + (mw + gid) * Fc + 2 * tig;
    const __half* Bb = Bg + (nw + gid) * Fc + 2 * tig;

    for (int k0 = 0; k0 < Fc; k0 += 16) {
        uint32_t a[2][4], b[4][2];
#pragma unroll
        for (int mf = 0; mf < 2; mf++) {
            const float* p = Ab + mf * 16 * Fc + k0;
            float2 f0 = *(const float2*)(p);
            float2 f1 = *(const float2*)(p + 8 * Fc);
            float2 f2 = *(const float2*)(p + 8);
            float2 f3 = *(const float2*)(p + 8 * Fc + 8);
            a[mf][0] = __half2_raw(__floats2half2_rn(f0.x, f0.y)).x |
                       ((uint32_t)__half2_raw(__floats2half2_rn(f0.x, f0.y)).y << 16);
            // (packing via raw is clunky; do it cleanly below)
            __half2 h0 = __floats2half2_rn(f0.x, f0.y);
            __half2 h1 = __floats2half2_rn(f1.x, f1.y);
            __half2 h2 = __floats2half2_rn(f2.x, f2.y);
            __half2 h3 = __floats2half2_rn(f3.x, f3.y);
            a[mf][0] = *(uint32_t*)&h0;
            a[mf][1] = *(uint32_t*)&h1;
            a[mf][2] = *(uint32_t*)&h2;
            a[mf][3] = *(uint32_t*)&h3;
        }
#pragma unroll
        for (int nf = 0; nf < 4; nf++) {
            const __half* p = Bb + nf * 8 * Fc + k0;
            b[nf][0] = *(const uint32_t*)(p);
            b[nf][1] = *(const uint32_t*)(p + 8);
        }
#pragma unroll
        for (int mf = 0; mf < 2; mf++)
#pragma unroll
            for (int nf = 0; nf < 4; nf++)
                mma16816(acc[mf][nf], a[mf], b[nf]);
    }

    // dkf epilogue
    const float invF = 1.0f / Fc;
#pragma unroll
    for (int mf = 0; mf < 2; mf++) {
#pragma unroll
        for (int h = 0; h < 2; h++) {
            const int gr = mw + mf * 16 + gid + h * 8;
#pragma unroll
            for (int nf = 0; nf < 4; nf++) {
                const int gc = nw + nf * 8 + 2 * tig;
                const int idx = gr * Fc + gc;
                const int cl = gc - n0;
                float v0 = acc[mf][nf][h * 2 + 0];
                float v1 = acc[mf][nf][h * 2 + 1];
                float2 wfv = *(const float2*)&wf32[idx];
                float2 xz  = *(const float2*)&g_XZ[idx];
                float2 o;
                o.x = s_diag[cl] * (xz.x - wfv.x * s_zbar[cl])
                    + wfv.x * s_r[cl] - v0 * invF;
                o.y = s_diag[cl + 1] * (xz.y - wfv.y * s_zbar[cl + 1])
                    + wfv.y * s_r[cl + 1] - v1 * invF;
                *(float2*)&o_dkf[idx] = o;
            }
        }
    }
}

extern "C" void kernel_launch(void* const* d_in, const int* in_sizes, int n_in,
                              void* d_out, int out_size)
{
    const float* z  = (const float*)d_in[0];   // (B,F)
    const float* x  = (const float*)d_in[1];   // (B,D)
    const float* u  = (const float*)d_in[2];   // (B,F)
    const float* td = (const float*)d_in[3];   // (B,F)
    const float* mu = (const float*)d_in[4];   // (F,F)
    const float* wf = (const float*)d_in[5];   // (D,F)

    float* out   = (float*)d_out;
    float* o_dmu = out;                        // F*F
    float* o_dkf = o_dmu + Fc * Fc;            // D*F
    float* o_dbf = o_dkf + Dc * Fc;            // F
    float* o_dkp = o_dbf + Fc;                 // F*F
    float* o_dbp = o_dkp + Fc * Fc;            // F

    conv_k<<<448, 256>>>(z, x, u, td);
    mma1_k<<<40, 256>>>(mu, o_dmu, o_dbf, o_dbp, o_dkp);
    mma2_k<<<16, 256>>>(wf, o_dkf);
}

// round 8
// speedup vs baseline: 1.6689x; 1.6689x over previous
#include <cuda_runtime.h>
#include <cuda_fp16.h>
#include <cstdint>

// Problem constants: B=256, D=256, F=512
#define Bc 256
#define Dc 256
#define Fc 512
#define P_T 0.05f

#define DEVARR __device__ __align__(16)
DEVARR __half g_G16[Fc * Fc];    // G fp16, rows i, cols j (k-major for mma2 B)
DEVARR float g_XZ[Dc * Fc];      // mean_b x z
DEVARR float g_zbar[Fc];
DEVARR float g_rpart[4][Fc];     // G row-sum partials per 128-col chunk (raw)
DEVARR float g_diag[Fc];         // p - mu_t[i,i]

__device__ __forceinline__ uint32_t smem_u32(const void* p) {
    uint32_t a;
    asm("{ .reg .u64 t; cvta.to.shared.u64 t, %1; cvt.u32.u64 %0, t; }"
        : "=r"(a) : "l"(p));
    return a;
}

// m16n8k16 f16 MMA, fp32 accumulate (verified R7)
__device__ __forceinline__ void mma16816(float* c, const uint32_t* a, const uint32_t* b) {
    asm volatile(
        "mma.sync.aligned.m16n8k16.row.col.f32.f16.f16.f32 "
        "{%0,%1,%2,%3}, {%4,%5,%6,%7}, {%8,%9}, {%0,%1,%2,%3};"
        : "+f"(c[0]), "+f"(c[1]), "+f"(c[2]), "+f"(c[3])
        : "r"(a[0]), "r"(a[1]), "r"(a[2]), "r"(a[3]), "r"(b[0]), "r"(b[1]));
}

__device__ __forceinline__ void ldsm_x4(uint32_t& r0, uint32_t& r1, uint32_t& r2,
                                        uint32_t& r3, uint32_t addr) {
    asm volatile("ldmatrix.sync.aligned.m8n8.x4.shared.b16 {%0,%1,%2,%3}, [%4];"
                 : "=r"(r0), "=r"(r1), "=r"(r2), "=r"(r3) : "r"(addr));
}
__device__ __forceinline__ void ldsm_x4_t(uint32_t& r0, uint32_t& r1, uint32_t& r2,
                                          uint32_t& r3, uint32_t addr) {
    asm volatile("ldmatrix.sync.aligned.m8n8.x4.trans.shared.b16 {%0,%1,%2,%3}, [%4];"
                 : "=r"(r0), "=r"(r1), "=r"(r2), "=r"(r3) : "r"(addr));
}

// ---------------------------------------------------------------------------
// mma1_k: 40 CTAs, 128x128 tiles, K=256 (4 kblocks of 64). 8 warps (2x4),
// warp tile 64x32 (mf=4, nf=4). Operands staged in smem (inline fp32->fp16),
// fragments via ldmatrix.trans (data is [k=b][m] natural layout).
//   bb [0,16):  M  = z'z /B  -> dmu, G16, rpart, diag/dbf/dbp (+zbar on diag)
//   bb [16,32): KP = u'td /B -> o_dkp
//   bb [32,40): XZ = x'z /B  -> g_XZ
// ---------------------------------------------------------------------------
__global__ void __launch_bounds__(256) mma1_k(
    const float* __restrict__ z, const float* __restrict__ x,
    const float* __restrict__ u, const float* __restrict__ td,
    const float* __restrict__ mu,
    float* __restrict__ o_dmu, float* __restrict__ o_dbf,
    float* __restrict__ o_dbp, float* __restrict__ o_dkp)
{
    __shared__ __align__(16) __half As[64][136];   // [k][m], stride 272B
    __shared__ __align__(16) __half Bs[64][136];   // [k][n]
    __shared__ float s_rsum[128];
    __shared__ __align__(16) float s_zsum[8][128];

    const int bb = blockIdx.x, tid = threadIdx.x;
    const int wid = tid >> 5, lane = tid & 31;
    const int gid = lane >> 2, tig = lane & 3;
    const int wm = wid >> 2, wn = wid & 3;        // 2x4 warp grid
    const int q = lane >> 3, r = lane & 7;        // ldmatrix lane decomp

    int kind, m0, n0, lda;
    const float *A, *B;
    if (bb < 16)      { kind = 0; int t = bb;      m0 = (t >> 2) * 128; n0 = (t & 3) * 128; A = z; B = z;  lda = Fc; }
    else if (bb < 32) { kind = 1; int t = bb - 16; m0 = (t >> 2) * 128; n0 = (t & 3) * 128; A = u; B = td; lda = Fc; }
    else              { kind = 2; int t = bb - 32; m0 = (t >> 2) * 128; n0 = (t & 3) * 128; A = x; B = z;  lda = Dc; }

    if (tid < 128) s_rsum[tid] = 0.f;

    float acc[4][4][4];
#pragma unroll
    for (int i = 0; i < 4; i++)
#pragma unroll
        for (int j = 0; j < 4; j++)
#pragma unroll
            for (int p = 0; p < 4; p++) acc[i][j][p] = 0.f;

    float4 zacc = {0.f, 0.f, 0.f, 0.f};           // zbar column partials

    const uint32_t smA = smem_u32(As), smB = smem_u32(Bs);
    // Per-lane ldmatrix.trans offsets (bytes):
    //  A mats: q0=(k0,m) q1=(k0,m+8) q2=(k0+8,m) q3=(k0+8,m+8)
    const uint32_t aLane = (uint32_t)(((((q & 2) ? 8 : 0) + r) * 136 + ((q & 1) ? 8 : 0)) * 2);
    //  B mats: q0=(k0,n) q1=(k0+8,n) q2=(k0,n+8) q3=(k0+8,n+8)
    const uint32_t bLane = (uint32_t)(((((q & 1) ? 8 : 0) + r) * 136 + ((q & 2) ? 8 : 0)) * 2);

    const int row0 = tid >> 5, cq = tid & 31;     // panel-load decomposition

    for (int kb = 0; kb < Bc; kb += 64) {
        // A panel: 64 rows (k) x 128 cols fp32 -> fp16
#pragma unroll
        for (int i = 0; i < 8; i++) {
            int row = row0 + i * 8;
            float4 v = *(const float4*)&A[(kb + row) * lda + m0 + 4 * cq];
            if (kind == 0) { zacc.x += v.x; zacc.y += v.y; zacc.z += v.z; zacc.w += v.w; }
            __half2 h0 = __floats2half2_rn(v.x, v.y);
            __half2 h1 = __floats2half2_rn(v.z, v.w);
            uint2 pk = {*(uint32_t*)&h0, *(uint32_t*)&h1};
            *(uint2*)&As[row][4 * cq] = pk;
        }
        // B panel
#pragma unroll
        for (int i = 0; i < 8; i++) {
            int row = row0 + i * 8;
            float4 v = *(const float4*)&B[(kb + row) * Fc + n0 + 4 * cq];
            __half2 h0 = __floats2half2_rn(v.x, v.y);
            __half2 h1 = __floats2half2_rn(v.z, v.w);
            uint2 pk = {*(uint32_t*)&h0, *(uint32_t*)&h1};
            *(uint2*)&Bs[row][4 * cq] = pk;
        }
        __syncthreads();
#pragma unroll
        for (int ks = 0; ks < 4; ks++) {
            const uint32_t koff = (uint32_t)(ks * 16) * 136u * 2u;
            uint32_t a[4][4], b[4][2];
#pragma unroll
            for (int mf = 0; mf < 4; mf++) {
                uint32_t addr = smA + aLane + koff + (uint32_t)(wm * 64 + mf * 16) * 2u;
                ldsm_x4_t(a[mf][0], a[mf][1], a[mf][2], a[mf][3], addr);
            }
#pragma unroll
            for (int np = 0; np < 2; np++) {
                uint32_t t0, t1, t2, t3;
                uint32_t addr = smB + bLane + koff + (uint32_t)(wn * 32 + np * 16) * 2u;
                ldsm_x4_t(t0, t1, t2, t3, addr);
                b[2 * np][0] = t0; b[2 * np][1] = t1;
                b[2 * np + 1][0] = t2; b[2 * np + 1][1] = t3;
            }
#pragma unroll
            for (int mf = 0; mf < 4; mf++)
#pragma unroll
                for (int nf = 0; nf < 4; nf++)
                    mma16816(acc[mf][nf], a[mf], b[nf]);
        }
        __syncthreads();
    }

    // Fused epilogue (verified in R7)
    const int mw = m0 + wm * 64, nw = n0 + wn * 32;
    const float invB = 1.0f / Bc;
#pragma unroll
    for (int mf = 0; mf < 4; mf++) {
#pragma unroll
        for (int h = 0; h < 2; h++) {
            const int gr = mw + mf * 16 + gid + h * 8;
            float rowsum = 0.f;
#pragma unroll
            for (int nf = 0; nf < 4; nf++) {
                const int gc = nw + nf * 8 + 2 * tig;
                const int idx = gr * Fc + gc;
                float v0 = acc[mf][nf][h * 2 + 0];
                float v1 = acc[mf][nf][h * 2 + 1];
                if (kind == 0) {
                    float raw0 = v0 * invB, raw1 = v1 * invB;
                    float2 muv = *(const float2*)&mu[idx];
                    float mut0 = 0.95f * muv.x + 0.05f * raw0;
                    float mut1 = 0.95f * muv.y + 0.05f * raw1;
                    float2 dm = {0.05f * (raw0 - muv.x), 0.05f * (raw1 - muv.y)};
                    *(float2*)&o_dmu[idx] = dm;
                    float G0 = (P_T * P_T - mut0) * raw0;
                    float G1 = (P_T * P_T - mut1) * raw1;
                    *(__half2*)&g_G16[idx] = __floats2half2_rn(G0, G1);
                    rowsum += G0 + G1;
                    if (m0 == n0) {
                        if (gr == gc) {
                            float db = P_T - mut0;
                            g_diag[gr] = db; o_dbf[gr] = db; o_dbp[gr] = db;
                        } else if (gr == gc + 1) {
                            float db = P_T - mut1;
                            g_diag[gr] = db; o_dbf[gr] = db; o_dbp[gr] = db;
                        }
                    }
                } else if (kind == 1) {
                    float2 o = {v0 * invB, v1 * invB};
                    *(float2*)&o_dkp[idx] = o;
                } else {
                    float2 o = {v0 * invB, v1 * invB};
                    *(float2*)&g_XZ[idx] = o;
                }
            }
            if (kind == 0) {
                rowsum += __shfl_xor_sync(0xffffffffu, rowsum, 1);
                rowsum += __shfl_xor_sync(0xffffffffu, rowsum, 2);
                if (tig == 0) atomicAdd(&s_rsum[gr - m0], rowsum);
            }
        }
    }
    if (kind == 0) {
        __syncthreads();
        if (tid < 128) g_rpart[n0 >> 7][m0 + tid] = s_rsum[tid];
        if (m0 == n0) {
            // zbar: combine per-thread column partials (thread covered rows
            // row0+8i+kb for fixed cols m0+4cq..+3 across the whole K loop)
            *(float4*)&s_zsum[row0][4 * cq] = zacc;
            __syncthreads();
            if (tid < 128) {
                float s = 0.f;
#pragma unroll
                for (int p = 0; p < 8; p++) s += s_zsum[p][tid];
                g_zbar[m0 + tid] = s * (1.0f / Bc);
            }
        }
    }
}

// ---------------------------------------------------------------------------
// mma2_k: 32 CTAs, 64x64 tiles, K=512 (8 kblocks of 64). 8 warps (2x4),
// warp tile 32x16 (mf=2, nf=2). A = wf (fp32->fp16 inline, [m][k] natural),
// B = G16 ([n][k] natural). Plain ldmatrix (no trans). Full dkf epilogue.
// ---------------------------------------------------------------------------
__global__ void __launch_bounds__(256) mma2_k(
    const float* __restrict__ wf32, float* __restrict__ o_dkf)
{
    __shared__ __align__(16) __half As[64][72];   // [m][k], stride 144B
    __shared__ __align__(16) __half Bs[64][72];   // [n][k]
    __shared__ float s_diag[64], s_zbar[64], s_r[64];

    const int bb = blockIdx.x, tid = threadIdx.x;
    const int wid = tid >> 5, lane = tid & 31;
    const int gid = lane >> 2, tig = lane & 3;
    const int wm = wid >> 2, wn = wid & 3;        // 2x4 warp grid
    const int q = lane >> 3, r = lane & 7;

    const int d0 = (bb >> 3) * 64;                // 4 row tiles
    const int n0 = (bb & 7) * 64;                 // 8 col tiles

    if (tid < 64) {
        int i = n0 + tid;
        s_zbar[tid] = g_zbar[i];
        float rr = 0.f;
#pragma unroll
        for (int p = 0; p < 4; p++) rr += g_rpart[p][i];
        s_r[tid] = rr * (1.0f / Fc);
        s_diag[tid] = g_diag[i];
    }

    float acc[2][2][4];
#pragma unroll
    for (int i = 0; i < 2; i++)
#pragma unroll
        for (int j = 0; j < 2; j++)
#pragma unroll
            for (int p = 0; p < 4; p++) acc[i][j][p] = 0.f;

    const uint32_t smA = smem_u32(As), smB = smem_u32(Bs);
    // no-trans lane offsets:
    //  A mats: q0=(m,k0) q1=(m+8,k0) q2=(m,k0+8) q3=(m+8,k0+8)
    const uint32_t aLane = (uint32_t)(((((q & 1) ? 8 : 0) + r) * 72 + ((q & 2) ? 8 : 0)) * 2);
    //  B mats: q0=(n,k0) q1=(n,k0+8) q2=(n+8,k0) q3=(n+8,k0+8)
    const uint32_t bLane = (uint32_t)(((((q & 2) ? 8 : 0) + r) * 72 + ((q & 1) ? 8 : 0)) * 2);

    const int rowA0 = tid >> 4, cqA = tid & 15;   // A panel decomp (4 iters)
    const int rowB0 = tid >> 3, cqB = tid & 7;    // B panel decomp (2 iters)

    for (int kb = 0; kb < Fc; kb += 64) {
        // A panel: wf fp32 -> fp16, 64 rows x 64 k
#pragma unroll
        for (int i = 0; i < 4; i++) {
            int row = rowA0 + i * 16;
            float4 v = *(const float4*)&wf32[(d0 + row) * Fc + kb + 4 * cqA];
            __half2 h0 = __floats2half2_rn(v.x, v.y);
            __half2 h1 = __floats2half2_rn(v.z, v.w);
            uint2 pk = {*(uint32_t*)&h0, *(uint32_t*)&h1};
            *(uint2*)&As[row][4 * cqA] = pk;
        }
        // B panel: G16 fp16 direct copy
#pragma unroll
        for (int i = 0; i < 2; i++) {
            int row = rowB0 + i * 32;
            uint4 v = *(const uint4*)&g_G16[(n0 + row) * Fc + kb + 8 * cqB];
            *(uint4*)&Bs[row][8 * cqB] = v;
        }
        __syncthreads();
#pragma unroll
        for (int ks = 0; ks < 4; ks++) {
            const uint32_t koff = (uint32_t)(ks * 16) * 2u;
            uint32_t a[2][4], b[2][2];
#pragma unroll
            for (int mf = 0; mf < 2; mf++) {
                uint32_t addr = smA + aLane + (uint32_t)((wm * 32 + mf * 16) * 72) * 2u + koff;
                ldsm_x4(a[mf][0], a[mf][1], a[mf][2], a[mf][3], addr);
            }
            {
                uint32_t t0, t1, t2, t3;
                uint32_t addr = smB + bLane + (uint32_t)((wn * 16) * 72) * 2u + koff;
                ldsm_x4(t0, t1, t2, t3, addr);
                b[0][0] = t0; b[0][1] = t1; b[1][0] = t2; b[1][1] = t3;
            }
#pragma unroll
            for (int mf = 0; mf < 2; mf++)
#pragma unroll
                for (int nf = 0; nf < 2; nf++)
                    mma16816(acc[mf][nf], a[mf], b[nf]);
        }
        __syncthreads();
    }

    // dkf epilogue
    const float invF = 1.0f / Fc;
    const int mw = d0 + wm * 32, nw = n0 + wn * 16;
#pragma unroll
    for (int mf = 0; mf < 2; mf++) {
#pragma unroll
        for (int h = 0; h < 2; h++) {
            const int gr = mw + mf * 16 + gid + h * 8;
#pragma unroll
            for (int nf = 0; nf < 2; nf++) {
                const int gc = nw + nf * 8 + 2 * tig;
                const int idx = gr * Fc + gc;
                const int cl = gc - n0;
                float v0 = acc[mf][nf][h * 2 + 0];
                float v1 = acc[mf][nf][h * 2 + 1];
                float2 wfv = *(const float2*)&wf32[idx];
                float2 xz  = *(const float2*)&g_XZ[idx];
                float2 o;
                o.x = s_diag[cl] * (xz.x - wfv.x * s_zbar[cl])
                    + wfv.x * s_r[cl] - v0 * invF;
                o.y = s_diag[cl + 1] * (xz.y - wfv.y * s_zbar[cl + 1])
                    + wfv.y * s_r[cl + 1] - v1 * invF;
                *(float2*)&o_dkf[idx] = o;
            }
        }
    }
}

extern "C" void kernel_launch(void* const* d_in, const int* in_sizes, int n_in,
                              void* d_out, int out_size)
{
    const float* z  = (const float*)d_in[0];   // (B,F)
    const float* x  = (const float*)d_in[1];   // (B,D)
    const float* u  = (const float*)d_in[2];   // (B,F)
    const float* td = (const float*)d_in[3];   // (B,F)
    const float* mu = (const float*)d_in[4];   // (F,F)
    const float* wf = (const float*)d_in[5];   // (D,F)

    float* out   = (float*)d_out;
    float* o_dmu = out;                        // F*F
    float* o_dkf = o_dmu + Fc * Fc;            // D*F
    float* o_dbf = o_dkf + Dc * Fc;            // F
    float* o_dkp = o_dbf + Fc;                 // F*F
    float* o_dbp = o_dkp + Fc * Fc;            // F

    mma1_k<<<40, 256>>>(z, x, u, td, mu, o_dmu, o_dbf, o_dbp, o_dkp);
    mma2_k<<<32, 256>>>(wf, o_dkf);
}

// round 9
// speedup vs baseline: 1.9408x; 1.1629x over previous
#include <cuda_runtime.h>
#include <cuda_fp16.h>
#include <cstdint>

// Problem constants: B=256, D=256, F=512
#define Bc 256
#define Dc 256
#define Fc 512
#define P_T 0.05f

#define DEVARR __device__ __align__(16)
DEVARR __half g_G16[Fc * Fc];    // G fp16, rows i, cols j
DEVARR __half g_wf16[Dc * Fc];   // wf fp16 (converted by mma1 kind-3 CTAs)
DEVARR float g_XZ[Dc * Fc];      // mean_b x z
DEVARR float g_zbar[Fc];
DEVARR float g_rpart[4][Fc];     // G row-sum partials per 128-col chunk (raw)
DEVARR float g_diag[Fc];         // p - mu_t[i,i]

__device__ __forceinline__ uint32_t smem_u32(const void* p) {
    uint32_t a;
    asm("{ .reg .u64 t; cvta.to.shared.u64 t, %1; cvt.u32.u64 %0, t; }"
        : "=r"(a) : "l"(p));
    return a;
}

// m16n8k16 f16 MMA, fp32 accumulate (verified R7/R8)
__device__ __forceinline__ void mma16816(float* c, const uint32_t* a, const uint32_t* b) {
    asm volatile(
        "mma.sync.aligned.m16n8k16.row.col.f32.f16.f16.f32 "
        "{%0,%1,%2,%3}, {%4,%5,%6,%7}, {%8,%9}, {%0,%1,%2,%3};"
        : "+f"(c[0]), "+f"(c[1]), "+f"(c[2]), "+f"(c[3])
        : "r"(a[0]), "r"(a[1]), "r"(a[2]), "r"(a[3]), "r"(b[0]), "r"(b[1]));
}
__device__ __forceinline__ void ldsm_x4(uint32_t& r0, uint32_t& r1, uint32_t& r2,
                                        uint32_t& r3, uint32_t addr) {
    asm volatile("ldmatrix.sync.aligned.m8n8.x4.shared.b16 {%0,%1,%2,%3}, [%4];"
                 : "=r"(r0), "=r"(r1), "=r"(r2), "=r"(r3) : "r"(addr));
}
__device__ __forceinline__ void ldsm_x4_t(uint32_t& r0, uint32_t& r1, uint32_t& r2,
                                          uint32_t& r3, uint32_t addr) {
    asm volatile("ldmatrix.sync.aligned.m8n8.x4.trans.shared.b16 {%0,%1,%2,%3}, [%4];"
                 : "=r"(r0), "=r"(r1), "=r"(r2), "=r"(r3) : "r"(addr));
}
__device__ __forceinline__ void cp16(uint32_t dst, const void* src) {
    asm volatile("cp.async.cg.shared.global [%0], [%1], 16;" :: "r"(dst), "l"(src));
}
__device__ __forceinline__ void cp_commit() {
    asm volatile("cp.async.commit_group;" ::: "memory");
}
template <int N>
__device__ __forceinline__ void cp_wait() {
    asm volatile("cp.async.wait_group %0;" :: "n"(N) : "memory");
}

// ---------------------------------------------------------------------------
// mma1_k: 56 CTAs. [0,40): gemm tiles as R8 (verified) with register-prefetch
// software pipeline. [40,56): wf fp32 -> fp16 conversion (for mma2).
// ---------------------------------------------------------------------------
__global__ void __launch_bounds__(256) mma1_k(
    const float* __restrict__ z, const float* __restrict__ x,
    const float* __restrict__ u, const float* __restrict__ td,
    const float* __restrict__ mu, const float* __restrict__ wf32,
    float* __restrict__ o_dmu, float* __restrict__ o_dbf,
    float* __restrict__ o_dbp, float* __restrict__ o_dkp)
{
    const int bb = blockIdx.x, tid = threadIdx.x;

    if (bb >= 40) {
        // wf conversion: 16 CTAs x 16384 floats
        const int base = (bb - 40) * 16384 + tid * 4;
#pragma unroll
        for (int q = 0; q < 16; q++) {
            const int off = base + q * 1024;
            float4 v = *(const float4*)&wf32[off];
            __half2 h0 = __floats2half2_rn(v.x, v.y);
            __half2 h1 = __floats2half2_rn(v.z, v.w);
            uint2 pk = {*(uint32_t*)&h0, *(uint32_t*)&h1};
            *(uint2*)&g_wf16[off] = pk;
        }
        return;
    }

    __shared__ __align__(16) __half As[64][136];   // [k][m]
    __shared__ __align__(16) __half Bs[64][136];   // [k][n]
    __shared__ float s_rsum[128];
    __shared__ __align__(16) float s_zsum[8][128];

    const int wid = tid >> 5, lane = tid & 31;
    const int gid = lane >> 2, tig = lane & 3;
    const int wm = wid >> 2, wn = wid & 3;        // 2x4 warp grid
    const int q = lane >> 3, r = lane & 7;

    int kind, m0, n0, lda;
    const float *A, *B;
    if (bb < 16)      { kind = 0; int t = bb;      m0 = (t >> 2) * 128; n0 = (t & 3) * 128; A = z; B = z;  lda = Fc; }
    else if (bb < 32) { kind = 1; int t = bb - 16; m0 = (t >> 2) * 128; n0 = (t & 3) * 128; A = u; B = td; lda = Fc; }
    else              { kind = 2; int t = bb - 32; m0 = (t >> 2) * 128; n0 = (t & 3) * 128; A = x; B = z;  lda = Dc; }

    if (tid < 128) s_rsum[tid] = 0.f;

    float acc[4][4][4];
#pragma unroll
    for (int i = 0; i < 4; i++)
#pragma unroll
        for (int j = 0; j < 4; j++)
#pragma unroll
            for (int p = 0; p < 4; p++) acc[i][j][p] = 0.f;

    float4 zacc = {0.f, 0.f, 0.f, 0.f};

    const uint32_t smA = smem_u32(As), smB = smem_u32(Bs);
    const uint32_t aLane = (uint32_t)(((((q & 2) ? 8 : 0) + r) * 136 + ((q & 1) ? 8 : 0)) * 2);
    const uint32_t bLane = (uint32_t)(((((q & 1) ? 8 : 0) + r) * 136 + ((q & 2) ? 8 : 0)) * 2);

    const int row0 = tid >> 5, cq = tid & 31;

    // ---- software pipeline: prefetch k-block into regs, STS, overlap next LDG
    float4 pa[8], pb[8];
#pragma unroll
    for (int i = 0; i < 8; i++) {
        int row = row0 + i * 8;
        pa[i] = *(const float4*)&A[row * lda + m0 + 4 * cq];
        pb[i] = *(const float4*)&B[row * Fc  + n0 + 4 * cq];
    }

#pragma unroll
    for (int kb = 0; kb < 4; kb++) {
        // STS + convert (and zbar accumulation for kind 0)
#pragma unroll
        for (int i = 0; i < 8; i++) {
            int row = row0 + i * 8;
            float4 v = pa[i];
            if (kind == 0) { zacc.x += v.x; zacc.y += v.y; zacc.z += v.z; zacc.w += v.w; }
            __half2 h0 = __floats2half2_rn(v.x, v.y);
            __half2 h1 = __floats2half2_rn(v.z, v.w);
            uint2 pk = {*(uint32_t*)&h0, *(uint32_t*)&h1};
            *(uint2*)&As[row][4 * cq] = pk;
            float4 w = pb[i];
            __half2 g0 = __floats2half2_rn(w.x, w.y);
            __half2 g1 = __floats2half2_rn(w.z, w.w);
            uint2 qk = {*(uint32_t*)&g0, *(uint32_t*)&g1};
            *(uint2*)&Bs[row][4 * cq] = qk;
        }
        __syncthreads();

        // issue LDGs for next block (overlaps with compute below)
        if (kb < 3) {
            const int kn = (kb + 1) * 64;
#pragma unroll
            for (int i = 0; i < 8; i++) {
                int row = kn + row0 + i * 8;
                pa[i] = *(const float4*)&A[row * lda + m0 + 4 * cq];
                pb[i] = *(const float4*)&B[row * Fc  + n0 + 4 * cq];
            }
        }

#pragma unroll
        for (int ks = 0; ks < 4; ks++) {
            const uint32_t koff = (uint32_t)(ks * 16) * 136u * 2u;
            uint32_t a[4][4], b[4][2];
#pragma unroll
            for (int mf = 0; mf < 4; mf++) {
                uint32_t addr = smA + aLane + koff + (uint32_t)(wm * 64 + mf * 16) * 2u;
                ldsm_x4_t(a[mf][0], a[mf][1], a[mf][2], a[mf][3], addr);
            }
#pragma unroll
            for (int np = 0; np < 2; np++) {
                uint32_t t0, t1, t2, t3;
                uint32_t addr = smB + bLane + koff + (uint32_t)(wn * 32 + np * 16) * 2u;
                ldsm_x4_t(t0, t1, t2, t3, addr);
                b[2 * np][0] = t0; b[2 * np][1] = t1;
                b[2 * np + 1][0] = t2; b[2 * np + 1][1] = t3;
            }
#pragma unroll
            for (int mf = 0; mf < 4; mf++)
#pragma unroll
                for (int nf = 0; nf < 4; nf++)
                    mma16816(acc[mf][nf], a[mf], b[nf]);
        }
        __syncthreads();
    }

    // Fused epilogue (verified R8)
    const int mw = m0 + wm * 64, nw = n0 + wn * 32;
    const float invB = 1.0f / Bc;
#pragma unroll
    for (int mf = 0; mf < 4; mf++) {
#pragma unroll
        for (int h = 0; h < 2; h++) {
            const int gr = mw + mf * 16 + gid + h * 8;
            float rowsum = 0.f;
#pragma unroll
            for (int nf = 0; nf < 4; nf++) {
                const int gc = nw + nf * 8 + 2 * tig;
                const int idx = gr * Fc + gc;
                float v0 = acc[mf][nf][h * 2 + 0];
                float v1 = acc[mf][nf][h * 2 + 1];
                if (kind == 0) {
                    float raw0 = v0 * invB, raw1 = v1 * invB;
                    float2 muv = *(const float2*)&mu[idx];
                    float mut0 = 0.95f * muv.x + 0.05f * raw0;
                    float mut1 = 0.95f * muv.y + 0.05f * raw1;
                    float2 dm = {0.05f * (raw0 - muv.x), 0.05f * (raw1 - muv.y)};
                    *(float2*)&o_dmu[idx] = dm;
                    float G0 = (P_T * P_T - mut0) * raw0;
                    float G1 = (P_T * P_T - mut1) * raw1;
                    *(__half2*)&g_G16[idx] = __floats2half2_rn(G0, G1);
                    rowsum += G0 + G1;
                    if (m0 == n0) {
                        if (gr == gc) {
                            float db = P_T - mut0;
                            g_diag[gr] = db; o_dbf[gr] = db; o_dbp[gr] = db;
                        } else if (gr == gc + 1) {
                            float db = P_T - mut1;
                            g_diag[gr] = db; o_dbf[gr] = db; o_dbp[gr] = db;
                        }
                    }
                } else if (kind == 1) {
                    float2 o = {v0 * invB, v1 * invB};
                    *(float2*)&o_dkp[idx] = o;
                } else {
                    float2 o = {v0 * invB, v1 * invB};
                    *(float2*)&g_XZ[idx] = o;
                }
            }
            if (kind == 0) {
                rowsum += __shfl_xor_sync(0xffffffffu, rowsum, 1);
                rowsum += __shfl_xor_sync(0xffffffffu, rowsum, 2);
                if (tig == 0) atomicAdd(&s_rsum[gr - m0], rowsum);
            }
        }
    }
    if (kind == 0) {
        __syncthreads();
        if (tid < 128) g_rpart[n0 >> 7][m0 + tid] = s_rsum[tid];
        if (m0 == n0) {
            *(float4*)&s_zsum[row0][4 * cq] = zacc;
            __syncthreads();
            if (tid < 128) {
                float s = 0.f;
#pragma unroll
                for (int p = 0; p < 8; p++) s += s_zsum[p][tid];
                g_zbar[m0 + tid] = s * (1.0f / Bc);
            }
        }
    }
}

// ---------------------------------------------------------------------------
// mma2_k: 32 CTAs, 64x64 tiles, K=512 (8 kblocks of 64), cp.async
// double-buffered fp16 panels (A=g_wf16, B=g_G16). Full dkf epilogue fused.
// ---------------------------------------------------------------------------
#define PBUF (64 * 72)   // halves per panel buffer

__global__ void __launch_bounds__(256) mma2_k(
    const float* __restrict__ wf32, float* __restrict__ o_dkf)
{
    __shared__ __align__(16) __half As[2][64][72];
    __shared__ __align__(16) __half Bs[2][64][72];
    __shared__ float s_diag[64], s_zbar[64], s_r[64];

    const int bb = blockIdx.x, tid = threadIdx.x;
    const int wid = tid >> 5, lane = tid & 31;
    const int gid = lane >> 2, tig = lane & 3;
    const int wm = wid >> 2, wn = wid & 3;        // 2x4 warp grid
    const int q = lane >> 3, r = lane & 7;

    const int d0 = (bb >> 3) * 64;
    const int n0 = (bb & 7) * 64;

    if (tid < 64) {
        int i = n0 + tid;
        s_zbar[tid] = g_zbar[i];
        float rr = 0.f;
#pragma unroll
        for (int p = 0; p < 4; p++) rr += g_rpart[p][i];
        s_r[tid] = rr * (1.0f / Fc);
        s_diag[tid] = g_diag[i];
    }

    float acc[2][2][4];
#pragma unroll
    for (int i = 0; i < 2; i++)
#pragma unroll
        for (int j = 0; j < 2; j++)
#pragma unroll
            for (int p = 0; p < 4; p++) acc[i][j][p] = 0.f;

    const uint32_t smA = smem_u32(As), smB = smem_u32(Bs);
    const uint32_t aLane = (uint32_t)(((((q & 1) ? 8 : 0) + r) * 72 + ((q & 2) ? 8 : 0)) * 2);
    const uint32_t bLane = (uint32_t)(((((q & 2) ? 8 : 0) + r) * 72 + ((q & 1) ? 8 : 0)) * 2);

    // cp.async mapping: thread -> row=tid>>2, 32B (2 chunks) at col=(tid&3)*16
    const int prow = tid >> 2, pcol = (tid & 3) * 16;
    const uint32_t pdst = (uint32_t)(prow * 72 + pcol) * 2u;

    auto issue = [&](int buf, int kb) {
        const __half* sa = g_wf16 + (d0 + prow) * Fc + kb + pcol;
        const __half* sb = g_G16  + (n0 + prow) * Fc + kb + pcol;
        uint32_t da = smA + (uint32_t)buf * (PBUF * 2u) + pdst;
        uint32_t db = smB + (uint32_t)buf * (PBUF * 2u) + pdst;
        cp16(da, sa); cp16(da + 16, sa + 8);
        cp16(db, sb); cp16(db + 16, sb + 8);
        cp_commit();
    };

    issue(0, 0);
#pragma unroll
    for (int kb8 = 0; kb8 < 8; kb8++) {
        if (kb8 < 7) { issue((kb8 + 1) & 1, (kb8 + 1) * 64); cp_wait<1>(); }
        else         { cp_wait<0>(); }
        __syncthreads();

        const uint32_t bufOff = (uint32_t)(kb8 & 1) * (PBUF * 2u);
#pragma unroll
        for (int ks = 0; ks < 4; ks++) {
            const uint32_t koff = (uint32_t)(ks * 16) * 2u;
            uint32_t a[2][4], b[2][2];
#pragma unroll
            for (int mf = 0; mf < 2; mf++) {
                uint32_t addr = smA + bufOff + aLane
                              + (uint32_t)((wm * 32 + mf * 16) * 72) * 2u + koff;
                ldsm_x4(a[mf][0], a[mf][1], a[mf][2], a[mf][3], addr);
            }
            {
                uint32_t t0, t1, t2, t3;
                uint32_t addr = smB + bufOff + bLane
                              + (uint32_t)((wn * 16) * 72) * 2u + koff;
                ldsm_x4(t0, t1, t2, t3, addr);
                b[0][0] = t0; b[0][1] = t1; b[1][0] = t2; b[1][1] = t3;
            }
#pragma unroll
            for (int mf = 0; mf < 2; mf++)
#pragma unroll
                for (int nf = 0; nf < 2; nf++)
                    mma16816(acc[mf][nf], a[mf], b[nf]);
        }
        __syncthreads();
    }

    // dkf epilogue (verified R8)
    const float invF = 1.0f / Fc;
    const int mw = d0 + wm * 32, nw = n0 + wn * 16;
#pragma unroll
    for (int mf = 0; mf < 2; mf++) {
#pragma unroll
        for (int h = 0; h < 2; h++) {
            const int gr = mw + mf * 16 + gid + h * 8;
#pragma unroll
            for (int nf = 0; nf < 2; nf++) {
                const int gc = nw + nf * 8 + 2 * tig;
                const int idx = gr * Fc + gc;
                const int cl = gc - n0;
                float v0 = acc[mf][nf][h * 2 + 0];
                float v1 = acc[mf][nf][h * 2 + 1];
                float2 wfv = *(const float2*)&wf32[idx];
                float2 xz  = *(const float2*)&g_XZ[idx];
                float2 o;
                o.x = s_diag[cl] * (xz.x - wfv.x * s_zbar[cl])
                    + wfv.x * s_r[cl] - v0 * invF;
                o.y = s_diag[cl + 1] * (xz.y - wfv.y * s_zbar[cl + 1])
                    + wfv.y * s_r[cl + 1] - v1 * invF;
                *(float2*)&o_dkf[idx] = o;
            }
        }
    }
}

extern "C" void kernel_launch(void* const* d_in, const int* in_sizes, int n_in,
                              void* d_out, int out_size)
{
    const float* z  = (const float*)d_in[0];   // (B,F)
    const float* x  = (const float*)d_in[1];   // (B,D)
    const float* u  = (const float*)d_in[2];   // (B,F)
    const float* td = (const float*)d_in[3];   // (B,F)
    const float* mu = (const float*)d_in[4];   // (F,F)
    const float* wf = (const float*)d_in[5];   // (D,F)

    float* out   = (float*)d_out;
    float* o_dmu = out;                        // F*F
    float* o_dkf = o_dmu + Fc * Fc;            // D*F
    float* o_dbf = o_dkf + Dc * Fc;            // F
    float* o_dkp = o_dbf + Fc;                 // F*F
    float* o_dbp = o_dkp + Fc * Fc;            // F

    mma1_k<<<56, 256>>>(z, x, u, td, mu, wf, o_dmu, o_dbf, o_dbp, o_dkp);
    mma2_k<<<32, 256>>>(wf, o_dkf);
}